// round 14
// baseline (speedup 1.0000x reference)
#include <cuda_runtime.h>
#include <cuda_fp16.h>
#include <math.h>

#define NMAX 50000
#define EMAX 800000
#define ETOT (NMAX + EMAX)
#define FULLM 0xffffffffu
#define NBLK ((NMAX + 1023) / 1024)
#define APAD 136   // halfs per padded smem row (128 + 8 -> conflict-free frags)

// ---------------- scratch (static device globals: no allocation allowed) ----
__device__ int   d_is64;
__device__ int   d_deg[NMAX];
__device__ int   d_rowptr[NMAX + 1];
__device__ int   d_rank[ETOT];       // per-edge rank within its dst row
__device__ int2  d_pair[ETOT];       // decoded {src, dst} per edge
__device__ int   d_tstate[NBLK];     // decoupled-lookback: 0 none, 1 agg, 2 incl
__device__ int   d_tagg[NBLK];
__device__ int   d_tinc[NBLK];
__device__ int   d_col[ETOT];
__device__ float d_hA[NMAX * 128];   // h2 buffer (fp16, reinterpreted)
__device__ float d_hB[NMAX * 128];   // z1 buffer  (fp16, reinterpreted)
__device__ float d_as[NMAX * 4];
__device__ float d_ad[NMAX * 4];
__device__ float d_cs[4];            // layer1 rank-1 alpha coefficients
__device__ float d_cd[4];
__device__ float2 d_p3[NMAX];        // packed {h3, as3}
__device__ float d_ad3[NMAX];

// ---------------- helpers ---------------------------------------------------
__device__ __forceinline__ float lrelu(float e) { return e > 0.f ? e : 0.2f * e; }

__device__ __forceinline__ float wredsum(float v) {
#pragma unroll
    for (int o = 16; o; o >>= 1) v += __shfl_xor_sync(FULLM, v, o);
    return v;
}
__device__ __forceinline__ int wincl(int x, int lane) {
#pragma unroll
    for (int o = 1; o < 32; o <<= 1) {
        int t = __shfl_up_sync(FULLM, x, o);
        if (lane >= o) x += t;
    }
    return x;
}
__device__ __forceinline__ float comp4(float4 v, int h) {
    float r = v.x;
    r = (h == 1) ? v.y : r;
    r = (h == 2) ? v.z : r;
    r = (h == 3) ? v.w : r;
    return r;
}

// ---------------- fused init: detect dtype + coef + zero deg + scan flags ---
__global__ void init_k(const void* ei, const float* __restrict__ W1,
                       const float* __restrict__ as1, const float* __restrict__ ad1,
                       int N) {
    int gtid = blockIdx.x * blockDim.x + threadIdx.x;
    for (int i = gtid; i < N; i += gridDim.x * blockDim.x) d_deg[i] = 0;
    if (gtid < NBLK) d_tstate[gtid] = 0;

    if (blockIdx.x == 0) {
        if (threadIdx.x < 32) {                      // warp 0: dtype detect
            int lane = threadIdx.x;
            const int* p = (const int*)ei;
            int bad = 0;
#pragma unroll
            for (int i = 0; i < 8; i++)
                bad |= (p[2 * (lane + i * 32) + 1] != 0);
            unsigned any = __ballot_sync(FULLM, bad);
            if (lane == 0) d_is64 = (any == 0) ? 1 : 0;
        } else if (threadIdx.x < 160) {              // warps 1-4: layer1 coefs
            int j = threadIdx.x - 32;                // 0..127, warp = head
            float w = W1[j];
            float ps = wredsum(w * as1[j]);
            float pd = wredsum(w * ad1[j]);
            if ((j & 31) == 0) {
                d_cs[j >> 5] = ps;
                d_cd[j >> 5] = pd;
            }
        }
    }
}

// ---------------- CSR build -------------------------------------------------
// hist: decode edges once, store pairs, degree count + per-edge rank
__global__ void hist_k(const void* ei, int E, int N) {
    int base = (blockIdx.x * blockDim.x + threadIdx.x) * 4;
    int tot = E + N;
    if (base >= tot) return;
    int is64 = d_is64;
    int srcs[4], dsts[4];
#pragma unroll
    for (int u = 0; u < 4; u++) {
        int e = base + u;
        int src = 0, dst = -1;
        if (e < tot) {
            if (e < E) {
                if (is64) {
                    const long long* p = (const long long*)ei;
                    src = (int)p[e];
                    dst = (int)p[(long long)E + e];
                } else {
                    const int* p = (const int*)ei;
                    src = p[e];
                    dst = p[E + e];
                }
            } else {
                src = dst = e - E;
            }
        }
        srcs[u] = src; dsts[u] = dst;
    }
#pragma unroll
    for (int u = 0; u < 4; u++) {
        if (dsts[u] >= 0) {
            d_pair[base + u] = make_int2(srcs[u], dsts[u]);
            int r = atomicAdd(&d_deg[dsts[u]], 1);
            d_rank[base + u] = r;
        }
    }
}

// single-pass scan, decoupled lookback (NBLK=49 blocks, all resident -> safe)
__global__ void scan_k(int N) {
    __shared__ int wsum[32];
    __shared__ int s_excl;
    int b = blockIdx.x;
    int i = b * 1024 + threadIdx.x;
    int lane = threadIdx.x & 31, wid = threadIdx.x >> 5;
    int v = (i < N) ? d_deg[i] : 0;
    int x = wincl(v, lane);
    if (lane == 31) wsum[wid] = x;
    __syncthreads();
    if (wid == 0) wsum[lane] = wincl(wsum[lane], lane);
    __syncthreads();
    int incl = x + (wid ? wsum[wid - 1] : 0);

    if (threadIdx.x == 0) {
        int agg = wsum[31];
        volatile int* st = d_tstate;
        if (b == 0) {
            d_tinc[0] = agg;
            __threadfence();
            st[0] = 2;
            s_excl = 0;
        } else {
            d_tagg[b] = agg;
            __threadfence();
            st[b] = 1;
            int run = 0;
            for (int j = b - 1; j >= 0; j--) {
                int s;
                do { s = st[j]; } while (s < 1);
                if (s == 2) { run += ((volatile int*)d_tinc)[j]; break; }
                run += ((volatile int*)d_tagg)[j];
            }
            d_tinc[b] = run + agg;
            __threadfence();
            st[b] = 2;
            s_excl = run;
        }
    }
    __syncthreads();
    int excl = s_excl;
    if (i < N) d_rowptr[i + 1] = incl + excl;
    if (i == 0) d_rowptr[0] = 0;
}

// atomic-free scatter from pre-decoded pairs: pos = rowptr[dst] + rank[e]
__global__ void scatter_k(int tot) {
    int base = (blockIdx.x * blockDim.x + threadIdx.x) * 4;
    if (base >= tot) return;
    int2 pr[4];
    int rnk[4];
#pragma unroll
    for (int u = 0; u < 4; u++) {
        int e = base + u;
        pr[u]  = (e < tot) ? d_pair[e] : make_int2(0, -1);
        rnk[u] = (e < tot) ? d_rank[e] : 0;
    }
    int pos[4];
#pragma unroll
    for (int u = 0; u < 4; u++)
        pos[u] = (pr[u].y >= 0) ? d_rowptr[pr[u].y] + rnk[u] : -1;
#pragma unroll
    for (int u = 0; u < 4; u++)
        if (pos[u] >= 0) d_col[pos[u]] = pr[u].x;
}

// ---------------- layer 1: rank-1 fused feature+aggregation (fp16 out) ------
__global__ void agg1_k(const float* __restrict__ x,
                       const float* __restrict__ W1, const float* __restrict__ b1,
                       __half* __restrict__ z_out, int N) {
    int w = (blockIdx.x * blockDim.x + threadIdx.x) >> 5;
    if (w >= N) return;
    int lane = threadIdx.x & 31;
    int start = d_rowptr[w], end = d_rowptr[w + 1];

    float4 cs = *((const float4*)d_cs);
    float4 cd = *((const float4*)d_cd);
    float xd = x[w];
    float ed0 = xd * cd.x, ed1 = xd * cd.y, ed2 = xd * cd.z, ed3 = xd * cd.w;

    float S0 = 0.f, S1 = 0.f, S2 = 0.f, S3 = 0.f;
    float T0 = 0.f, T1 = 0.f, T2 = 0.f, T3 = 0.f;
    for (int i = start + lane; i < end; i += 32) {
        int s = d_col[i];
        float xs = x[s];
        float w0 = __expf(lrelu(xs * cs.x + ed0));
        float w1 = __expf(lrelu(xs * cs.y + ed1));
        float w2 = __expf(lrelu(xs * cs.z + ed2));
        float w3 = __expf(lrelu(xs * cs.w + ed3));
        S0 += w0; S1 += w1; S2 += w2; S3 += w3;
        T0 = fmaf(w0, xs, T0); T1 = fmaf(w1, xs, T1);
        T2 = fmaf(w2, xs, T2); T3 = fmaf(w3, xs, T3);
    }
    S0 = wredsum(S0); S1 = wredsum(S1); S2 = wredsum(S2); S3 = wredsum(S3);
    T0 = wredsum(T0); T1 = wredsum(T1); T2 = wredsum(T2); T3 = wredsum(T3);

    float t = comp4(make_float4(T0 / S0, T1 / S1, T2 / S2, T3 / S3), lane >> 3);

    float4 W4 = ((const float4*)W1)[lane];
    float4 b4 = ((const float4*)b1)[lane];
    float4 v = make_float4(fmaf(W4.x, t, b4.x), fmaf(W4.y, t, b4.y),
                           fmaf(W4.z, t, b4.z), fmaf(W4.w, t, b4.w));
    v.x = v.x > 0.f ? v.x : expm1f(v.x);
    v.y = v.y > 0.f ? v.y : expm1f(v.y);
    v.z = v.z > 0.f ? v.z : expm1f(v.z);
    v.w = v.w > 0.f ? v.w : expm1f(v.w);

    __half2 p0 = __floats2half2_rn(v.x, v.y);
    __half2 p1 = __floats2half2_rn(v.z, v.w);
    uint2 pk;
    pk.x = *(unsigned*)&p0;
    pk.y = *(unsigned*)&p1;
    ((uint2*)z_out)[w * 32 + lane] = pk;
}

// ---------------- layer 2 GEMM on tensor cores + fused alphas ---------------
__device__ __forceinline__ void mma16816(float c[4], const unsigned a[4],
                                         unsigned b0, unsigned b1) {
    asm volatile(
        "mma.sync.aligned.m16n8k16.row.col.f32.f16.f16.f32 "
        "{%0,%1,%2,%3}, {%4,%5,%6,%7}, {%8,%9}, {%0,%1,%2,%3};\n"
        : "+f"(c[0]), "+f"(c[1]), "+f"(c[2]), "+f"(c[3])
        : "r"(a[0]), "r"(a[1]), "r"(a[2]), "r"(a[3]), "r"(b0), "r"(b1));
}

__global__ void gemm_tc(const __half* __restrict__ zin, const float* __restrict__ W2,
                        const float* __restrict__ as2, const float* __restrict__ ad2,
                        __half* __restrict__ h_out, int N) {
    extern __shared__ __half hsm[];           // A:128*APAD, B:128*APAD
    __half* Asm = hsm;
    __half* Bsm = hsm + 128 * APAD;
    int tid = threadIdx.x;
    int lane = tid & 31, warp = tid >> 5;
    int warp_m = warp >> 1, warp_n = warp & 1; // 4 x 2 warp grid

    for (int idx = tid; idx < 128 * 128; idx += 256) {
        int k = idx >> 7, n = idx & 127;
        Bsm[n * APAD + k] = __float2half(W2[idx]);
    }

    int r0 = warp_m * 32 + (lane >> 2);
    int kcol = (lane & 3) * 2;
    int headA = warp_n * 2, headB = warp_n * 2 + 1;

    for (int tile = blockIdx.x * 128; tile < N; tile += gridDim.x * 128) {
        __syncthreads();
        for (int idx = tid; idx < 128 * 16; idx += 256) {
            int m = idx >> 4, kb = idx & 15;
            int node = tile + m;
            uint4 v = make_uint4(0u, 0u, 0u, 0u);
            if (node < N) v = ((const uint4*)(zin + node * 128))[kb];
            *((uint4*)(Asm + m * APAD + kb * 8)) = v;
        }
        __syncthreads();

        float c[2][8][4];
#pragma unroll
        for (int mt = 0; mt < 2; mt++)
#pragma unroll
            for (int nt = 0; nt < 8; nt++)
#pragma unroll
                for (int q = 0; q < 4; q++) c[mt][nt][q] = 0.f;

#pragma unroll
        for (int ks = 0; ks < 8; ks++) {
            int k0 = ks * 16 + kcol;
            unsigned a[2][4];
#pragma unroll
            for (int mt = 0; mt < 2; mt++) {
                int r = r0 + mt * 16;
                a[mt][0] = *(const unsigned*)(Asm + r * APAD + k0);
                a[mt][1] = *(const unsigned*)(Asm + (r + 8) * APAD + k0);
                a[mt][2] = *(const unsigned*)(Asm + r * APAD + k0 + 8);
                a[mt][3] = *(const unsigned*)(Asm + (r + 8) * APAD + k0 + 8);
            }
#pragma unroll
            for (int nt = 0; nt < 8; nt++) {
                int n = warp_n * 64 + nt * 8 + (lane >> 2);
                unsigned b0 = *(const unsigned*)(Bsm + n * APAD + k0);
                unsigned b1 = *(const unsigned*)(Bsm + n * APAD + k0 + 8);
                mma16816(c[0][nt], a[0], b0, b1);
                mma16816(c[1][nt], a[1], b0, b1);
            }
        }

        // epilogue: store fp16 h2 + alphas from fp32 accumulators
#pragma unroll
        for (int mt = 0; mt < 2; mt++) {
#pragma unroll
            for (int half = 0; half < 2; half++) {
                int r = r0 + mt * 16 + half * 8;
                int node = tile + r;
                float psA = 0.f, pdA = 0.f, psB = 0.f, pdB = 0.f;
#pragma unroll
                for (int nt = 0; nt < 8; nt++) {
                    int col = warp_n * 64 + nt * 8 + (lane & 3) * 2;
                    float c0 = c[mt][nt][half * 2];
                    float c1 = c[mt][nt][half * 2 + 1];
                    float2 av = *(const float2*)(as2 + col);
                    float2 dv = *(const float2*)(ad2 + col);
                    float ps = c0 * av.x + c1 * av.y;
                    float pd = c0 * dv.x + c1 * dv.y;
                    if (nt < 4) { psA += ps; pdA += pd; }
                    else        { psB += ps; pdB += pd; }
                    if (node < N) {
                        __half2 p = __floats2half2_rn(c0, c1);
                        *(__half2*)(h_out + node * 128 + col) = p;
                    }
                }
                psA += __shfl_xor_sync(FULLM, psA, 1);
                psA += __shfl_xor_sync(FULLM, psA, 2);
                psB += __shfl_xor_sync(FULLM, psB, 1);
                psB += __shfl_xor_sync(FULLM, psB, 2);
                pdA += __shfl_xor_sync(FULLM, pdA, 1);
                pdA += __shfl_xor_sync(FULLM, pdA, 2);
                pdB += __shfl_xor_sync(FULLM, pdB, 1);
                pdB += __shfl_xor_sync(FULLM, pdB, 2);
                if ((lane & 3) == 0 && node < N) {
                    d_as[node * 4 + headA] = psA;
                    d_as[node * 4 + headB] = psB;
                    d_ad[node * 4 + headA] = pdA;
                    d_ad[node * 4 + headB] = pdB;
                }
            }
        }
    }
}

// ---------------- layer 2 aggregation, chunked shuffle-broadcast ------------
// Phase A per 32-edge chunk: lanes-over-edges -> coalesced col load, parallel
// alpha gathers, 4 exps/lane. Phase B: serial FMA over the chunk with s and
// the 4 head-weights coming from __shfl (no memory on the critical chain;
// feature-row loads are mutually independent -> MLP ~= chunk size).
__global__ void agg2_k(const __half* __restrict__ h_in,
                       const float* __restrict__ bias,
                       const float* __restrict__ w3,
                       const float* __restrict__ a3s, const float* __restrict__ a3d,
                       int N) {
    int w = (blockIdx.x * blockDim.x + threadIdx.x) >> 5;
    if (w >= N) return;
    int lane = threadIdx.x & 31;
    int start = d_rowptr[w], end = d_rowptr[w + 1];

    int myh = lane >> 3;
    float4 adv = ((const float4*)d_ad)[w];

    float S0 = 0.f, S1 = 0.f, S2 = 0.f, S3 = 0.f;
    float4 acc = make_float4(0.f, 0.f, 0.f, 0.f);

    for (int base = start; base < end; base += 32) {
        int i = base + lane;
        int valid = (i < end);
        int s_l = valid ? d_col[i] : 0;
        float w0 = 0.f, w1 = 0.f, w2 = 0.f, w3w = 0.f;
        if (valid) {
            float4 av = ((const float4*)d_as)[s_l];
            w0 = __expf(lrelu(av.x + adv.x));
            w1 = __expf(lrelu(av.y + adv.y));
            w2 = __expf(lrelu(av.z + adv.z));
            w3w = __expf(lrelu(av.w + adv.w));
        }
        S0 += w0; S1 += w1; S2 += w2; S3 += w3w;

        int cnt = end - base;
        if (cnt > 32) cnt = 32;
        for (int j = 0; j < cnt; j++) {
            int s = __shfl_sync(FULLM, s_l, j);
            float g0 = __shfl_sync(FULLM, w0, j);
            float g1 = __shfl_sync(FULLM, w1, j);
            float g2 = __shfl_sync(FULLM, w2, j);
            float g3 = __shfl_sync(FULLM, w3w, j);
            float wgt = comp4(make_float4(g0, g1, g2, g3), myh);
            uint2 hv = ((const uint2*)h_in)[s * 32 + lane];
            float2 f0 = __half22float2(*(__half2*)&hv.x);
            float2 f1 = __half22float2(*(__half2*)&hv.y);
            acc.x = fmaf(wgt, f0.x, acc.x);
            acc.y = fmaf(wgt, f0.y, acc.y);
            acc.z = fmaf(wgt, f1.x, acc.z);
            acc.w = fmaf(wgt, f1.y, acc.w);
        }
    }
    S0 = wredsum(S0); S1 = wredsum(S1); S2 = wredsum(S2); S3 = wredsum(S3);
    float inv = comp4(make_float4(1.f / S0, 1.f / S1, 1.f / S2, 1.f / S3), myh);

    float4 bv = ((const float4*)bias)[lane];
    float4 v = make_float4(fmaf(acc.x, inv, bv.x), fmaf(acc.y, inv, bv.y),
                           fmaf(acc.z, inv, bv.z), fmaf(acc.w, inv, bv.w));
    v.x = v.x > 0.f ? v.x : expm1f(v.x);
    v.y = v.y > 0.f ? v.y : expm1f(v.y);
    v.z = v.z > 0.f ? v.z : expm1f(v.z);
    v.w = v.w > 0.f ? v.w : expm1f(v.w);

    float4 w4 = ((const float4*)w3)[lane];
    float p = v.x * w4.x + v.y * w4.y + v.z * w4.z + v.w * w4.w;
    p = wredsum(p);
    if (lane == 0) {
        d_p3[w]  = make_float2(p, p * a3s[0]);  // {h3, as3} packed
        d_ad3[w] = p * a3d[0];
    }
}

// ---------------- layer 3 aggregation, half-warp (16 lanes) per node --------
__global__ void agg3_k(const float* __restrict__ b3, float* __restrict__ out, int N) {
    int w = (blockIdx.x * blockDim.x + threadIdx.x) >> 4;
    if (w >= N) return;
    int l16 = threadIdx.x & 15;
    int start = d_rowptr[w], end = d_rowptr[w + 1];
    float adn = d_ad3[w];

    float ss = 0.f, ws = 0.f;
    for (int i = start + l16; i < end; i += 16) {
        int s = d_col[i];
        float2 pv = d_p3[s];
        float wv = __expf(lrelu(pv.y + adn));
        ss += wv;
        ws += wv * pv.x;
    }
#pragma unroll
    for (int o = 8; o; o >>= 1) {           // stays within the 16-lane group
        ss += __shfl_xor_sync(FULLM, ss, o);
        ws += __shfl_xor_sync(FULLM, ws, o);
    }
    if (l16 == 0) out[w] = ws / ss + b3[0];
}

// ---------------- host launcher ---------------------------------------------
extern "C" void kernel_launch(void* const* d_in, const int* in_sizes, int n_in,
                              void* d_out, int out_size) {
    const float* x   = (const float*)d_in[0];
    const void*  ei  = d_in[1];
    const float* W1  = (const float*)d_in[2];
    const float* as1 = (const float*)d_in[3];
    const float* ad1 = (const float*)d_in[4];
    const float* b1  = (const float*)d_in[5];
    const float* W2  = (const float*)d_in[6];
    const float* as2 = (const float*)d_in[7];
    const float* ad2 = (const float*)d_in[8];
    const float* b2  = (const float*)d_in[9];
    const float* W3  = (const float*)d_in[10];
    const float* a3s = (const float*)d_in[11];
    const float* a3d = (const float*)d_in[12];
    const float* b3  = (const float*)d_in[13];
    float* out = (float*)d_out;

    int N = in_sizes[0];
    int E = in_sizes[1] / 2;
    if (N > NMAX) N = NMAX;
    if (E > EMAX) E = EMAX;
    int tot = E + N;

    float* hA; cudaGetSymbolAddress((void**)&hA, d_hA);
    float* hB; cudaGetSymbolAddress((void**)&hB, d_hB);

    init_k<<<(N + 255) / 256, 256>>>(ei, W1, as1, ad1, N);
    int e4_blocks = ((tot + 3) / 4 + 255) / 256;
    hist_k<<<e4_blocks, 256>>>(ei, E, N);
    scan_k<<<NBLK, 1024>>>(N);
    scatter_k<<<e4_blocks, 256>>>(tot);

    int agg_blocks = (N * 32 + 255) / 256;

    // layer 1 (rank-1 factorized, fp16 z1 out)
    agg1_k<<<agg_blocks, 256>>>(x, W1, b1, (__half*)hB, N);

    // layer 2: tensor-core GEMM (+fused alphas) + aggregation (+layer-3 feat)
    size_t smem = 2 * 128 * APAD * sizeof(__half);
    cudaFuncSetAttribute(gemm_tc, cudaFuncAttributeMaxDynamicSharedMemorySize, (int)smem);
    gemm_tc<<<296, 256, smem>>>((const __half*)hB, W2, as2, ad2, (__half*)hA, N);
    agg2_k<<<agg_blocks, 256>>>((const __half*)hA, b2, W3, a3s, a3d, N);

    // layer 3
    agg3_k<<<(N * 16 + 255) / 256, 256>>>(b3, out, N);
}

// round 15
// speedup vs baseline: 1.1297x; 1.1297x over previous
#include <cuda_runtime.h>
#include <cuda_fp16.h>
#include <math.h>

#define NMAX 50000
#define EMAX 800000
#define ETOT (NMAX + EMAX)
#define FULLM 0xffffffffu
#define NBLK ((NMAX + 1023) / 1024)
#define APAD 136   // halfs per padded smem row (128 + 8 -> conflict-free frags)

// ---------------- scratch (static device globals: no allocation allowed) ----
__device__ int   d_is64;
__device__ int   d_deg[NMAX];
__device__ int   d_rowptr[NMAX + 1];
__device__ int   d_rank[ETOT];       // per-edge rank within its dst row
__device__ int   d_tstate[NBLK];     // decoupled-lookback: 0 none, 1 agg, 2 incl
__device__ int   d_tagg[NBLK];
__device__ int   d_tinc[NBLK];
__device__ int   d_col[ETOT];
__device__ float d_hA[NMAX * 128];   // h2 buffer (fp16, reinterpreted)
__device__ float d_hB[NMAX * 128];   // z1 buffer  (fp16, reinterpreted)
__device__ float d_as[NMAX * 4];
__device__ float d_ad[NMAX * 4];
__device__ float d_cs[4];            // layer1 rank-1 alpha coefficients
__device__ float d_cd[4];
__device__ float2 d_p3[NMAX];        // packed {h3, as3}
__device__ float d_ad3[NMAX];

// ---------------- helpers ---------------------------------------------------
__device__ __forceinline__ float lrelu(float e) { return e > 0.f ? e : 0.2f * e; }

__device__ __forceinline__ float wredsum(float v) {
#pragma unroll
    for (int o = 16; o; o >>= 1) v += __shfl_xor_sync(FULLM, v, o);
    return v;
}
__device__ __forceinline__ int wincl(int x, int lane) {
#pragma unroll
    for (int o = 1; o < 32; o <<= 1) {
        int t = __shfl_up_sync(FULLM, x, o);
        if (lane >= o) x += t;
    }
    return x;
}
__device__ __forceinline__ float comp4(float4 v, int h) {
    float r = v.x;
    r = (h == 1) ? v.y : r;
    r = (h == 2) ? v.z : r;
    r = (h == 3) ? v.w : r;
    return r;
}

// ---------------- fused init: detect dtype + coef + zero deg + scan flags ---
__global__ void init_k(const void* ei, const float* __restrict__ W1,
                       const float* __restrict__ as1, const float* __restrict__ ad1,
                       int N) {
    int gtid = blockIdx.x * blockDim.x + threadIdx.x;
    for (int i = gtid; i < N; i += gridDim.x * blockDim.x) d_deg[i] = 0;
    if (gtid < NBLK) d_tstate[gtid] = 0;

    if (blockIdx.x == 0) {
        if (threadIdx.x < 32) {                      // warp 0: dtype detect
            int lane = threadIdx.x;
            const int* p = (const int*)ei;
            int bad = 0;
#pragma unroll
            for (int i = 0; i < 8; i++)
                bad |= (p[2 * (lane + i * 32) + 1] != 0);
            unsigned any = __ballot_sync(FULLM, bad);
            if (lane == 0) d_is64 = (any == 0) ? 1 : 0;
        } else if (threadIdx.x < 160) {              // warps 1-4: layer1 coefs
            int j = threadIdx.x - 32;                // 0..127, warp = head
            float w = W1[j];
            float ps = wredsum(w * as1[j]);
            float pd = wredsum(w * ad1[j]);
            if ((j & 31) == 0) {
                d_cs[j >> 5] = ps;
                d_cd[j >> 5] = pd;
            }
        }
    }
}

// ---------------- CSR build -------------------------------------------------
// hist: degree count + per-edge rank (atomicAdd return value)
__global__ void hist_k(const void* ei, int E, int N) {
    int base = (blockIdx.x * blockDim.x + threadIdx.x) * 4;
    int tot = E + N;
    if (base >= tot) return;
    int is64 = d_is64;
    int dsts[4];
#pragma unroll
    for (int u = 0; u < 4; u++) {
        int e = base + u;
        int dst = -1;
        if (e < tot) {
            if (e < E) {
                dst = is64 ? (int)((const long long*)ei)[(long long)E + e]
                           : ((const int*)ei)[E + e];
            } else {
                dst = e - E;
            }
        }
        dsts[u] = dst;
    }
#pragma unroll
    for (int u = 0; u < 4; u++) {
        if (dsts[u] >= 0) {
            int r = atomicAdd(&d_deg[dsts[u]], 1);
            d_rank[base + u] = r;
        }
    }
}

// single-pass scan, decoupled lookback (NBLK=49 blocks, all resident -> safe)
__global__ void scan_k(int N) {
    __shared__ int wsum[32];
    __shared__ int s_excl;
    int b = blockIdx.x;
    int i = b * 1024 + threadIdx.x;
    int lane = threadIdx.x & 31, wid = threadIdx.x >> 5;
    int v = (i < N) ? d_deg[i] : 0;
    int x = wincl(v, lane);
    if (lane == 31) wsum[wid] = x;
    __syncthreads();
    if (wid == 0) wsum[lane] = wincl(wsum[lane], lane);
    __syncthreads();
    int incl = x + (wid ? wsum[wid - 1] : 0);

    if (threadIdx.x == 0) {
        int agg = wsum[31];
        volatile int* st = d_tstate;
        if (b == 0) {
            d_tinc[0] = agg;
            __threadfence();
            st[0] = 2;
            s_excl = 0;
        } else {
            d_tagg[b] = agg;
            __threadfence();
            st[b] = 1;
            int run = 0;
            for (int j = b - 1; j >= 0; j--) {
                int s;
                do { s = st[j]; } while (s < 1);
                if (s == 2) { run += ((volatile int*)d_tinc)[j]; break; }
                run += ((volatile int*)d_tagg)[j];
            }
            d_tinc[b] = run + agg;
            __threadfence();
            st[b] = 2;
            s_excl = run;
        }
    }
    __syncthreads();
    int excl = s_excl;
    if (i < N) d_rowptr[i + 1] = incl + excl;
    if (i == 0) d_rowptr[0] = 0;
}

// atomic-free scatter: pos = rowptr[dst] + rank[e] (re-decode edge list)
__global__ void scatter_k(const void* ei, int E, int N) {
    int base = (blockIdx.x * blockDim.x + threadIdx.x) * 4;
    int tot = E + N;
    if (base >= tot) return;
    int is64 = d_is64;
    int srcs[4], dsts[4], rnks[4];
#pragma unroll
    for (int u = 0; u < 4; u++) {
        int e = base + u;
        int src = 0, dst = -1, rk = 0;
        if (e < tot) {
            if (e < E) {
                if (is64) {
                    const long long* p = (const long long*)ei;
                    src = (int)p[e];
                    dst = (int)p[(long long)E + e];
                } else {
                    const int* p = (const int*)ei;
                    src = p[e];
                    dst = p[E + e];
                }
            } else {
                src = dst = e - E;
            }
            rk = d_rank[e];
        }
        srcs[u] = src; dsts[u] = dst; rnks[u] = rk;
    }
    int pos[4];
#pragma unroll
    for (int u = 0; u < 4; u++)
        pos[u] = (dsts[u] >= 0) ? d_rowptr[dsts[u]] + rnks[u] : -1;
#pragma unroll
    for (int u = 0; u < 4; u++)
        if (pos[u] >= 0) d_col[pos[u]] = srcs[u];
}

// ---------------- layer 1: rank-1 fused feature+aggregation (fp16 out) ------
__global__ void agg1_k(const float* __restrict__ x,
                       const float* __restrict__ W1, const float* __restrict__ b1,
                       __half* __restrict__ z_out, int N) {
    int w = (blockIdx.x * blockDim.x + threadIdx.x) >> 5;
    if (w >= N) return;
    int lane = threadIdx.x & 31;
    int start = d_rowptr[w], end = d_rowptr[w + 1];

    float4 cs = *((const float4*)d_cs);
    float4 cd = *((const float4*)d_cd);
    float xd = x[w];
    float ed0 = xd * cd.x, ed1 = xd * cd.y, ed2 = xd * cd.z, ed3 = xd * cd.w;

    float S0 = 0.f, S1 = 0.f, S2 = 0.f, S3 = 0.f;
    float T0 = 0.f, T1 = 0.f, T2 = 0.f, T3 = 0.f;
    for (int i = start + lane; i < end; i += 32) {
        int s = d_col[i];
        float xs = x[s];
        float w0 = __expf(lrelu(xs * cs.x + ed0));
        float w1 = __expf(lrelu(xs * cs.y + ed1));
        float w2 = __expf(lrelu(xs * cs.z + ed2));
        float w3 = __expf(lrelu(xs * cs.w + ed3));
        S0 += w0; S1 += w1; S2 += w2; S3 += w3;
        T0 = fmaf(w0, xs, T0); T1 = fmaf(w1, xs, T1);
        T2 = fmaf(w2, xs, T2); T3 = fmaf(w3, xs, T3);
    }
    S0 = wredsum(S0); S1 = wredsum(S1); S2 = wredsum(S2); S3 = wredsum(S3);
    T0 = wredsum(T0); T1 = wredsum(T1); T2 = wredsum(T2); T3 = wredsum(T3);

    float t = comp4(make_float4(T0 / S0, T1 / S1, T2 / S2, T3 / S3), lane >> 3);

    float4 W4 = ((const float4*)W1)[lane];
    float4 b4 = ((const float4*)b1)[lane];
    float4 v = make_float4(fmaf(W4.x, t, b4.x), fmaf(W4.y, t, b4.y),
                           fmaf(W4.z, t, b4.z), fmaf(W4.w, t, b4.w));
    v.x = v.x > 0.f ? v.x : expm1f(v.x);
    v.y = v.y > 0.f ? v.y : expm1f(v.y);
    v.z = v.z > 0.f ? v.z : expm1f(v.z);
    v.w = v.w > 0.f ? v.w : expm1f(v.w);

    __half2 p0 = __floats2half2_rn(v.x, v.y);
    __half2 p1 = __floats2half2_rn(v.z, v.w);
    uint2 pk;
    pk.x = *(unsigned*)&p0;
    pk.y = *(unsigned*)&p1;
    ((uint2*)z_out)[w * 32 + lane] = pk;
}

// ---------------- layer 2 GEMM on tensor cores + fused alphas ---------------
__device__ __forceinline__ void mma16816(float c[4], const unsigned a[4],
                                         unsigned b0, unsigned b1) {
    asm volatile(
        "mma.sync.aligned.m16n8k16.row.col.f32.f16.f16.f32 "
        "{%0,%1,%2,%3}, {%4,%5,%6,%7}, {%8,%9}, {%0,%1,%2,%3};\n"
        : "+f"(c[0]), "+f"(c[1]), "+f"(c[2]), "+f"(c[3])
        : "r"(a[0]), "r"(a[1]), "r"(a[2]), "r"(a[3]), "r"(b0), "r"(b1));
}

__global__ void gemm_tc(const __half* __restrict__ zin, const float* __restrict__ W2,
                        const float* __restrict__ as2, const float* __restrict__ ad2,
                        __half* __restrict__ h_out, int N) {
    extern __shared__ __half hsm[];           // A:128*APAD, B:128*APAD
    __half* Asm = hsm;
    __half* Bsm = hsm + 128 * APAD;
    int tid = threadIdx.x;
    int lane = tid & 31, warp = tid >> 5;
    int warp_m = warp >> 1, warp_n = warp & 1; // 4 x 2 warp grid

    for (int idx = tid; idx < 128 * 128; idx += 256) {
        int k = idx >> 7, n = idx & 127;
        Bsm[n * APAD + k] = __float2half(W2[idx]);
    }

    int r0 = warp_m * 32 + (lane >> 2);
    int kcol = (lane & 3) * 2;
    int headA = warp_n * 2, headB = warp_n * 2 + 1;

    for (int tile = blockIdx.x * 128; tile < N; tile += gridDim.x * 128) {
        __syncthreads();
        for (int idx = tid; idx < 128 * 16; idx += 256) {
            int m = idx >> 4, kb = idx & 15;
            int node = tile + m;
            uint4 v = make_uint4(0u, 0u, 0u, 0u);
            if (node < N) v = ((const uint4*)(zin + node * 128))[kb];
            *((uint4*)(Asm + m * APAD + kb * 8)) = v;
        }
        __syncthreads();

        float c[2][8][4];
#pragma unroll
        for (int mt = 0; mt < 2; mt++)
#pragma unroll
            for (int nt = 0; nt < 8; nt++)
#pragma unroll
                for (int q = 0; q < 4; q++) c[mt][nt][q] = 0.f;

#pragma unroll
        for (int ks = 0; ks < 8; ks++) {
            int k0 = ks * 16 + kcol;
            unsigned a[2][4];
#pragma unroll
            for (int mt = 0; mt < 2; mt++) {
                int r = r0 + mt * 16;
                a[mt][0] = *(const unsigned*)(Asm + r * APAD + k0);
                a[mt][1] = *(const unsigned*)(Asm + (r + 8) * APAD + k0);
                a[mt][2] = *(const unsigned*)(Asm + r * APAD + k0 + 8);
                a[mt][3] = *(const unsigned*)(Asm + (r + 8) * APAD + k0 + 8);
            }
#pragma unroll
            for (int nt = 0; nt < 8; nt++) {
                int n = warp_n * 64 + nt * 8 + (lane >> 2);
                unsigned b0 = *(const unsigned*)(Bsm + n * APAD + k0);
                unsigned b1 = *(const unsigned*)(Bsm + n * APAD + k0 + 8);
                mma16816(c[0][nt], a[0], b0, b1);
                mma16816(c[1][nt], a[1], b0, b1);
            }
        }

        // epilogue: store fp16 h2 + alphas from fp32 accumulators
#pragma unroll
        for (int mt = 0; mt < 2; mt++) {
#pragma unroll
            for (int half = 0; half < 2; half++) {
                int r = r0 + mt * 16 + half * 8;
                int node = tile + r;
                float psA = 0.f, pdA = 0.f, psB = 0.f, pdB = 0.f;
#pragma unroll
                for (int nt = 0; nt < 8; nt++) {
                    int col = warp_n * 64 + nt * 8 + (lane & 3) * 2;
                    float c0 = c[mt][nt][half * 2];
                    float c1 = c[mt][nt][half * 2 + 1];
                    float2 av = *(const float2*)(as2 + col);
                    float2 dv = *(const float2*)(ad2 + col);
                    float ps = c0 * av.x + c1 * av.y;
                    float pd = c0 * dv.x + c1 * dv.y;
                    if (nt < 4) { psA += ps; pdA += pd; }
                    else        { psB += ps; pdB += pd; }
                    if (node < N) {
                        __half2 p = __floats2half2_rn(c0, c1);
                        *(__half2*)(h_out + node * 128 + col) = p;
                    }
                }
                psA += __shfl_xor_sync(FULLM, psA, 1);
                psA += __shfl_xor_sync(FULLM, psA, 2);
                psB += __shfl_xor_sync(FULLM, psB, 1);
                psB += __shfl_xor_sync(FULLM, psB, 2);
                pdA += __shfl_xor_sync(FULLM, pdA, 1);
                pdA += __shfl_xor_sync(FULLM, pdA, 2);
                pdB += __shfl_xor_sync(FULLM, pdB, 1);
                pdB += __shfl_xor_sync(FULLM, pdB, 2);
                if ((lane & 3) == 0 && node < N) {
                    d_as[node * 4 + headA] = psA;
                    d_as[node * 4 + headB] = psB;
                    d_ad[node * 4 + headA] = pdA;
                    d_ad[node * 4 + headB] = pdB;
                }
            }
        }
    }
}

// ---------------- layer 2 aggregation, single sweep, warp per dst node ------
__global__ void agg2_k(const __half* __restrict__ h_in,
                       const float* __restrict__ bias,
                       const float* __restrict__ w3,
                       const float* __restrict__ a3s, const float* __restrict__ a3d,
                       int N) {
    int w = (blockIdx.x * blockDim.x + threadIdx.x) >> 5;
    if (w >= N) return;
    int lane = threadIdx.x & 31;
    int start = d_rowptr[w], end = d_rowptr[w + 1];

    int myh = lane >> 3;
    float adh = d_ad[w * 4 + myh];

    float sw = 0.f;
    float4 acc = make_float4(0.f, 0.f, 0.f, 0.f);
#pragma unroll 2
    for (int i = start; i < end; i++) {
        int s = d_col[i];
        float av = d_as[s * 4 + myh];
        float wgt = __expf(lrelu(av + adh));
        sw += wgt;
        uint2 hv = ((const uint2*)h_in)[s * 32 + lane];
        float2 f0 = __half22float2(*(__half2*)&hv.x);
        float2 f1 = __half22float2(*(__half2*)&hv.y);
        acc.x = fmaf(wgt, f0.x, acc.x);
        acc.y = fmaf(wgt, f0.y, acc.y);
        acc.z = fmaf(wgt, f1.x, acc.z);
        acc.w = fmaf(wgt, f1.y, acc.w);
    }
    float inv = 1.f / sw;

    float4 bv = ((const float4*)bias)[lane];
    float4 v = make_float4(fmaf(acc.x, inv, bv.x), fmaf(acc.y, inv, bv.y),
                           fmaf(acc.z, inv, bv.z), fmaf(acc.w, inv, bv.w));
    v.x = v.x > 0.f ? v.x : expm1f(v.x);
    v.y = v.y > 0.f ? v.y : expm1f(v.y);
    v.z = v.z > 0.f ? v.z : expm1f(v.z);
    v.w = v.w > 0.f ? v.w : expm1f(v.w);

    float4 w4 = ((const float4*)w3)[lane];
    float p = v.x * w4.x + v.y * w4.y + v.z * w4.z + v.w * w4.w;
    p = wredsum(p);
    if (lane == 0) {
        d_p3[w]  = make_float2(p, p * a3s[0]);  // {h3, as3} packed
        d_ad3[w] = p * a3d[0];
    }
}

// ---------------- layer 3 aggregation (H=1, C=1), warp per dst node ---------
__global__ void agg3_k(const float* __restrict__ b3, float* __restrict__ out, int N) {
    int w = (blockIdx.x * blockDim.x + threadIdx.x) >> 5;
    if (w >= N) return;
    int lane = threadIdx.x & 31;
    int start = d_rowptr[w], end = d_rowptr[w + 1];
    float adn = d_ad3[w];

    float ss = 0.f, ws = 0.f;
    for (int i = start + lane; i < end; i += 32) {
        int s = d_col[i];
        float2 pv = d_p3[s];
        float wv = __expf(lrelu(pv.y + adn));
        ss += wv;
        ws += wv * pv.x;
    }
    ss = wredsum(ss);
    ws = wredsum(ws);
    if (lane == 0) out[w] = ws / ss + b3[0];
}

// ---------------- host launcher ---------------------------------------------
extern "C" void kernel_launch(void* const* d_in, const int* in_sizes, int n_in,
                              void* d_out, int out_size) {
    const float* x   = (const float*)d_in[0];
    const void*  ei  = d_in[1];
    const float* W1  = (const float*)d_in[2];
    const float* as1 = (const float*)d_in[3];
    const float* ad1 = (const float*)d_in[4];
    const float* b1  = (const float*)d_in[5];
    const float* W2  = (const float*)d_in[6];
    const float* as2 = (const float*)d_in[7];
    const float* ad2 = (const float*)d_in[8];
    const float* b2  = (const float*)d_in[9];
    const float* W3  = (const float*)d_in[10];
    const float* a3s = (const float*)d_in[11];
    const float* a3d = (const float*)d_in[12];
    const float* b3  = (const float*)d_in[13];
    float* out = (float*)d_out;

    int N = in_sizes[0];
    int E = in_sizes[1] / 2;
    if (N > NMAX) N = NMAX;
    if (E > EMAX) E = EMAX;
    int tot = E + N;

    float* hA; cudaGetSymbolAddress((void**)&hA, d_hA);
    float* hB; cudaGetSymbolAddress((void**)&hB, d_hB);

    init_k<<<(N + 255) / 256, 256>>>(ei, W1, as1, ad1, N);
    int e4_blocks = ((tot + 3) / 4 + 255) / 256;
    hist_k<<<e4_blocks, 256>>>(ei, E, N);
    scan_k<<<NBLK, 1024>>>(N);
    scatter_k<<<e4_blocks, 256>>>(ei, E, N);

    int agg_blocks = (N * 32 + 255) / 256;

    // layer 1 (rank-1 factorized, fp16 z1 out)
    agg1_k<<<agg_blocks, 256>>>(x, W1, b1, (__half*)hB, N);

    // layer 2: tensor-core GEMM (+fused alphas) + aggregation (+layer-3 feat)
    size_t smem = 2 * 128 * APAD * sizeof(__half);
    cudaFuncSetAttribute(gemm_tc, cudaFuncAttributeMaxDynamicSharedMemorySize, (int)smem);
    gemm_tc<<<296, 256, smem>>>((const __half*)hB, W2, as2, ad2, (__half*)hA, N);
    agg2_k<<<agg_blocks, 256>>>((const __half*)hA, b2, W3, a3s, a3d, N);

    // layer 3
    agg3_k<<<(N * 32 + 255) / 256, 256>>>(b3, out, N);
}

// round 16
// speedup vs baseline: 1.1327x; 1.0026x over previous
#include <cuda_runtime.h>
#include <cuda_fp16.h>
#include <math.h>

#define NMAX 50000
#define EMAX 800000
#define ETOT (NMAX + EMAX)
#define FULLM 0xffffffffu
#define NBLK ((NMAX + 1023) / 1024)
#define APAD 136   // halfs per padded smem row (128 + 8 -> conflict-free frags)

// ---------------- scratch (static device globals: no allocation allowed) ----
__device__ int   d_is64;
__device__ int   d_deg[NMAX];
__device__ int   d_rowptr[NMAX + 1];
__device__ int   d_rank[ETOT];       // per-edge rank within its dst row
__device__ int   d_tstate[NBLK];     // decoupled-lookback: 0 none, 1 agg, 2 incl
__device__ int   d_tagg[NBLK];
__device__ int   d_tinc[NBLK];
__device__ int   d_col[ETOT];
__device__ float d_hA[NMAX * 128];   // h2 buffer (fp16, reinterpreted)
__device__ float d_hB[NMAX * 128];   // z1 buffer  (fp16, reinterpreted)
__device__ float d_as[NMAX * 4];
__device__ float d_ad[NMAX * 4];
__device__ float d_cs[4];            // layer1 rank-1 alpha coefficients
__device__ float d_cd[4];
__device__ float2 d_p3[NMAX];        // packed {h3, as3}
__device__ float d_ad3[NMAX];

// ---------------- helpers ---------------------------------------------------
__device__ __forceinline__ float lrelu(float e) { return e > 0.f ? e : 0.2f * e; }

__device__ __forceinline__ float wredsum(float v) {
#pragma unroll
    for (int o = 16; o; o >>= 1) v += __shfl_xor_sync(FULLM, v, o);
    return v;
}
__device__ __forceinline__ int wincl(int x, int lane) {
#pragma unroll
    for (int o = 1; o < 32; o <<= 1) {
        int t = __shfl_up_sync(FULLM, x, o);
        if (lane >= o) x += t;
    }
    return x;
}
__device__ __forceinline__ float comp4(float4 v, int h) {
    float r = v.x;
    r = (h == 1) ? v.y : r;
    r = (h == 2) ? v.z : r;
    r = (h == 3) ? v.w : r;
    return r;
}

// ---------------- fused init: detect dtype + coef + zero deg + scan flags ---
__global__ void init_k(const void* ei, const float* __restrict__ W1,
                       const float* __restrict__ as1, const float* __restrict__ ad1,
                       int N) {
    int gtid = blockIdx.x * blockDim.x + threadIdx.x;
    for (int i = gtid; i < N; i += gridDim.x * blockDim.x) d_deg[i] = 0;
    if (gtid < NBLK) d_tstate[gtid] = 0;

    if (blockIdx.x == 0) {
        if (threadIdx.x < 32) {                      // warp 0: dtype detect
            int lane = threadIdx.x;
            const int* p = (const int*)ei;
            int bad = 0;
#pragma unroll
            for (int i = 0; i < 8; i++)
                bad |= (p[2 * (lane + i * 32) + 1] != 0);
            unsigned any = __ballot_sync(FULLM, bad);
            if (lane == 0) d_is64 = (any == 0) ? 1 : 0;
        } else if (threadIdx.x < 160) {              // warps 1-4: layer1 coefs
            int j = threadIdx.x - 32;                // 0..127, warp = head
            float w = W1[j];
            float ps = wredsum(w * as1[j]);
            float pd = wredsum(w * ad1[j]);
            if ((j & 31) == 0) {
                d_cs[j >> 5] = ps;
                d_cd[j >> 5] = pd;
            }
        }
    }
}

// ---------------- CSR build -------------------------------------------------
// hist: degree count + per-edge rank (atomicAdd return value).
// STRIDED 4-edge batching: e = gtid + u*T -> every load fully coalesced.
__global__ void hist_k(const void* ei, int E, int N, int T) {
    int gtid = blockIdx.x * blockDim.x + threadIdx.x;
    int tot = E + N;
    int is64 = d_is64;
    int es[4], dsts[4];
#pragma unroll
    for (int u = 0; u < 4; u++) {
        int e = gtid + u * T;
        int dst = -1;
        if (e < tot) {
            if (e < E) {
                dst = is64 ? (int)((const long long*)ei)[(long long)E + e]
                           : ((const int*)ei)[E + e];
            } else {
                dst = e - E;
            }
        }
        es[u] = e; dsts[u] = dst;
    }
#pragma unroll
    for (int u = 0; u < 4; u++) {
        if (dsts[u] >= 0) {
            int r = atomicAdd(&d_deg[dsts[u]], 1);
            d_rank[es[u]] = r;
        }
    }
}

// single-pass scan, decoupled lookback (NBLK=49 blocks, all resident -> safe)
__global__ void scan_k(int N) {
    __shared__ int wsum[32];
    __shared__ int s_excl;
    int b = blockIdx.x;
    int i = b * 1024 + threadIdx.x;
    int lane = threadIdx.x & 31, wid = threadIdx.x >> 5;
    int v = (i < N) ? d_deg[i] : 0;
    int x = wincl(v, lane);
    if (lane == 31) wsum[wid] = x;
    __syncthreads();
    if (wid == 0) wsum[lane] = wincl(wsum[lane], lane);
    __syncthreads();
    int incl = x + (wid ? wsum[wid - 1] : 0);

    if (threadIdx.x == 0) {
        int agg = wsum[31];
        volatile int* st = d_tstate;
        if (b == 0) {
            d_tinc[0] = agg;
            __threadfence();
            st[0] = 2;
            s_excl = 0;
        } else {
            d_tagg[b] = agg;
            __threadfence();
            st[b] = 1;
            int run = 0;
            for (int j = b - 1; j >= 0; j--) {
                int s;
                do { s = st[j]; } while (s < 1);
                if (s == 2) { run += ((volatile int*)d_tinc)[j]; break; }
                run += ((volatile int*)d_tagg)[j];
            }
            d_tinc[b] = run + agg;
            __threadfence();
            st[b] = 2;
            s_excl = run;
        }
    }
    __syncthreads();
    int excl = s_excl;
    if (i < N) d_rowptr[i + 1] = incl + excl;
    if (i == 0) d_rowptr[0] = 0;
}

// atomic-free scatter: pos = rowptr[dst] + rank[e]; strided coalesced batches
__global__ void scatter_k(const void* ei, int E, int N, int T) {
    int gtid = blockIdx.x * blockDim.x + threadIdx.x;
    int tot = E + N;
    int is64 = d_is64;
    int srcs[4], dsts[4], rnks[4];
#pragma unroll
    for (int u = 0; u < 4; u++) {
        int e = gtid + u * T;
        int src = 0, dst = -1, rk = 0;
        if (e < tot) {
            if (e < E) {
                if (is64) {
                    const long long* p = (const long long*)ei;
                    src = (int)p[e];
                    dst = (int)p[(long long)E + e];
                } else {
                    const int* p = (const int*)ei;
                    src = p[e];
                    dst = p[E + e];
                }
            } else {
                src = dst = e - E;
            }
            rk = d_rank[e];
        }
        srcs[u] = src; dsts[u] = dst; rnks[u] = rk;
    }
    int pos[4];
#pragma unroll
    for (int u = 0; u < 4; u++)
        pos[u] = (dsts[u] >= 0) ? d_rowptr[dsts[u]] + rnks[u] : -1;
#pragma unroll
    for (int u = 0; u < 4; u++)
        if (pos[u] >= 0) d_col[pos[u]] = srcs[u];
}

// ---------------- layer 1: rank-1 fused feature+aggregation (fp16 out) ------
__global__ void agg1_k(const float* __restrict__ x,
                       const float* __restrict__ W1, const float* __restrict__ b1,
                       __half* __restrict__ z_out, int N) {
    int w = (blockIdx.x * blockDim.x + threadIdx.x) >> 5;
    if (w >= N) return;
    int lane = threadIdx.x & 31;
    int start = d_rowptr[w], end = d_rowptr[w + 1];

    float4 cs = *((const float4*)d_cs);
    float4 cd = *((const float4*)d_cd);
    float xd = x[w];
    float ed0 = xd * cd.x, ed1 = xd * cd.y, ed2 = xd * cd.z, ed3 = xd * cd.w;

    float S0 = 0.f, S1 = 0.f, S2 = 0.f, S3 = 0.f;
    float T0 = 0.f, T1 = 0.f, T2 = 0.f, T3 = 0.f;
    for (int i = start + lane; i < end; i += 32) {
        int s = d_col[i];
        float xs = x[s];
        float w0 = __expf(lrelu(xs * cs.x + ed0));
        float w1 = __expf(lrelu(xs * cs.y + ed1));
        float w2 = __expf(lrelu(xs * cs.z + ed2));
        float w3 = __expf(lrelu(xs * cs.w + ed3));
        S0 += w0; S1 += w1; S2 += w2; S3 += w3;
        T0 = fmaf(w0, xs, T0); T1 = fmaf(w1, xs, T1);
        T2 = fmaf(w2, xs, T2); T3 = fmaf(w3, xs, T3);
    }
    S0 = wredsum(S0); S1 = wredsum(S1); S2 = wredsum(S2); S3 = wredsum(S3);
    T0 = wredsum(T0); T1 = wredsum(T1); T2 = wredsum(T2); T3 = wredsum(T3);

    float t = comp4(make_float4(T0 / S0, T1 / S1, T2 / S2, T3 / S3), lane >> 3);

    float4 W4 = ((const float4*)W1)[lane];
    float4 b4 = ((const float4*)b1)[lane];
    float4 v = make_float4(fmaf(W4.x, t, b4.x), fmaf(W4.y, t, b4.y),
                           fmaf(W4.z, t, b4.z), fmaf(W4.w, t, b4.w));
    v.x = v.x > 0.f ? v.x : expm1f(v.x);
    v.y = v.y > 0.f ? v.y : expm1f(v.y);
    v.z = v.z > 0.f ? v.z : expm1f(v.z);
    v.w = v.w > 0.f ? v.w : expm1f(v.w);

    __half2 p0 = __floats2half2_rn(v.x, v.y);
    __half2 p1 = __floats2half2_rn(v.z, v.w);
    uint2 pk;
    pk.x = *(unsigned*)&p0;
    pk.y = *(unsigned*)&p1;
    ((uint2*)z_out)[w * 32 + lane] = pk;
}

// ---------------- layer 2 GEMM on tensor cores + fused alphas ---------------
__device__ __forceinline__ void mma16816(float c[4], const unsigned a[4],
                                         unsigned b0, unsigned b1) {
    asm volatile(
        "mma.sync.aligned.m16n8k16.row.col.f32.f16.f16.f32 "
        "{%0,%1,%2,%3}, {%4,%5,%6,%7}, {%8,%9}, {%0,%1,%2,%3};\n"
        : "+f"(c[0]), "+f"(c[1]), "+f"(c[2]), "+f"(c[3])
        : "r"(a[0]), "r"(a[1]), "r"(a[2]), "r"(a[3]), "r"(b0), "r"(b1));
}

__global__ void gemm_tc(const __half* __restrict__ zin, const float* __restrict__ W2,
                        const float* __restrict__ as2, const float* __restrict__ ad2,
                        __half* __restrict__ h_out, int N) {
    extern __shared__ __half hsm[];           // A:128*APAD, B:128*APAD
    __half* Asm = hsm;
    __half* Bsm = hsm + 128 * APAD;
    int tid = threadIdx.x;
    int lane = tid & 31, warp = tid >> 5;
    int warp_m = warp >> 1, warp_n = warp & 1; // 4 x 2 warp grid

    for (int idx = tid; idx < 128 * 128; idx += 256) {
        int k = idx >> 7, n = idx & 127;
        Bsm[n * APAD + k] = __float2half(W2[idx]);
    }

    int r0 = warp_m * 32 + (lane >> 2);
    int kcol = (lane & 3) * 2;
    int headA = warp_n * 2, headB = warp_n * 2 + 1;

    for (int tile = blockIdx.x * 128; tile < N; tile += gridDim.x * 128) {
        __syncthreads();
        for (int idx = tid; idx < 128 * 16; idx += 256) {
            int m = idx >> 4, kb = idx & 15;
            int node = tile + m;
            uint4 v = make_uint4(0u, 0u, 0u, 0u);
            if (node < N) v = ((const uint4*)(zin + node * 128))[kb];
            *((uint4*)(Asm + m * APAD + kb * 8)) = v;
        }
        __syncthreads();

        float c[2][8][4];
#pragma unroll
        for (int mt = 0; mt < 2; mt++)
#pragma unroll
            for (int nt = 0; nt < 8; nt++)
#pragma unroll
                for (int q = 0; q < 4; q++) c[mt][nt][q] = 0.f;

#pragma unroll
        for (int ks = 0; ks < 8; ks++) {
            int k0 = ks * 16 + kcol;
            unsigned a[2][4];
#pragma unroll
            for (int mt = 0; mt < 2; mt++) {
                int r = r0 + mt * 16;
                a[mt][0] = *(const unsigned*)(Asm + r * APAD + k0);
                a[mt][1] = *(const unsigned*)(Asm + (r + 8) * APAD + k0);
                a[mt][2] = *(const unsigned*)(Asm + r * APAD + k0 + 8);
                a[mt][3] = *(const unsigned*)(Asm + (r + 8) * APAD + k0 + 8);
            }
#pragma unroll
            for (int nt = 0; nt < 8; nt++) {
                int n = warp_n * 64 + nt * 8 + (lane >> 2);
                unsigned b0 = *(const unsigned*)(Bsm + n * APAD + k0);
                unsigned b1 = *(const unsigned*)(Bsm + n * APAD + k0 + 8);
                mma16816(c[0][nt], a[0], b0, b1);
                mma16816(c[1][nt], a[1], b0, b1);
            }
        }

        // epilogue: store fp16 h2 + alphas from fp32 accumulators
#pragma unroll
        for (int mt = 0; mt < 2; mt++) {
#pragma unroll
            for (int half = 0; half < 2; half++) {
                int r = r0 + mt * 16 + half * 8;
                int node = tile + r;
                float psA = 0.f, pdA = 0.f, psB = 0.f, pdB = 0.f;
#pragma unroll
                for (int nt = 0; nt < 8; nt++) {
                    int col = warp_n * 64 + nt * 8 + (lane & 3) * 2;
                    float c0 = c[mt][nt][half * 2];
                    float c1 = c[mt][nt][half * 2 + 1];
                    float2 av = *(const float2*)(as2 + col);
                    float2 dv = *(const float2*)(ad2 + col);
                    float ps = c0 * av.x + c1 * av.y;
                    float pd = c0 * dv.x + c1 * dv.y;
                    if (nt < 4) { psA += ps; pdA += pd; }
                    else        { psB += ps; pdB += pd; }
                    if (node < N) {
                        __half2 p = __floats2half2_rn(c0, c1);
                        *(__half2*)(h_out + node * 128 + col) = p;
                    }
                }
                psA += __shfl_xor_sync(FULLM, psA, 1);
                psA += __shfl_xor_sync(FULLM, psA, 2);
                psB += __shfl_xor_sync(FULLM, psB, 1);
                psB += __shfl_xor_sync(FULLM, psB, 2);
                pdA += __shfl_xor_sync(FULLM, pdA, 1);
                pdA += __shfl_xor_sync(FULLM, pdA, 2);
                pdB += __shfl_xor_sync(FULLM, pdB, 1);
                pdB += __shfl_xor_sync(FULLM, pdB, 2);
                if ((lane & 3) == 0 && node < N) {
                    d_as[node * 4 + headA] = psA;
                    d_as[node * 4 + headB] = psB;
                    d_ad[node * 4 + headA] = pdA;
                    d_ad[node * 4 + headB] = pdB;
                }
            }
        }
    }
}

// ---------------- layer 2 aggregation, single sweep, warp per dst node ------
__global__ void agg2_k(const __half* __restrict__ h_in,
                       const float* __restrict__ bias,
                       const float* __restrict__ w3,
                       const float* __restrict__ a3s, const float* __restrict__ a3d,
                       int N) {
    int w = (blockIdx.x * blockDim.x + threadIdx.x) >> 5;
    if (w >= N) return;
    int lane = threadIdx.x & 31;
    int start = d_rowptr[w], end = d_rowptr[w + 1];

    int myh = lane >> 3;
    float adh = d_ad[w * 4 + myh];

    float sw = 0.f;
    float4 acc = make_float4(0.f, 0.f, 0.f, 0.f);
#pragma unroll 2
    for (int i = start; i < end; i++) {
        int s = d_col[i];
        float av = d_as[s * 4 + myh];
        float wgt = __expf(lrelu(av + adh));
        sw += wgt;
        uint2 hv = ((const uint2*)h_in)[s * 32 + lane];
        float2 f0 = __half22float2(*(__half2*)&hv.x);
        float2 f1 = __half22float2(*(__half2*)&hv.y);
        acc.x = fmaf(wgt, f0.x, acc.x);
        acc.y = fmaf(wgt, f0.y, acc.y);
        acc.z = fmaf(wgt, f1.x, acc.z);
        acc.w = fmaf(wgt, f1.y, acc.w);
    }
    float inv = 1.f / sw;

    float4 bv = ((const float4*)bias)[lane];
    float4 v = make_float4(fmaf(acc.x, inv, bv.x), fmaf(acc.y, inv, bv.y),
                           fmaf(acc.z, inv, bv.z), fmaf(acc.w, inv, bv.w));
    v.x = v.x > 0.f ? v.x : expm1f(v.x);
    v.y = v.y > 0.f ? v.y : expm1f(v.y);
    v.z = v.z > 0.f ? v.z : expm1f(v.z);
    v.w = v.w > 0.f ? v.w : expm1f(v.w);

    float4 w4 = ((const float4*)w3)[lane];
    float p = v.x * w4.x + v.y * w4.y + v.z * w4.z + v.w * w4.w;
    p = wredsum(p);
    if (lane == 0) {
        d_p3[w]  = make_float2(p, p * a3s[0]);  // {h3, as3} packed
        d_ad3[w] = p * a3d[0];
    }
}

// ---------------- layer 3 aggregation (H=1, C=1), warp per dst node ---------
__global__ void agg3_k(const float* __restrict__ b3, float* __restrict__ out, int N) {
    int w = (blockIdx.x * blockDim.x + threadIdx.x) >> 5;
    if (w >= N) return;
    int lane = threadIdx.x & 31;
    int start = d_rowptr[w], end = d_rowptr[w + 1];
    float adn = d_ad3[w];

    float ss = 0.f, ws = 0.f;
    for (int i = start + lane; i < end; i += 32) {
        int s = d_col[i];
        float2 pv = d_p3[s];
        float wv = __expf(lrelu(pv.y + adn));
        ss += wv;
        ws += wv * pv.x;
    }
    ss = wredsum(ss);
    ws = wredsum(ws);
    if (lane == 0) out[w] = ws / ss + b3[0];
}

// ---------------- host launcher ---------------------------------------------
extern "C" void kernel_launch(void* const* d_in, const int* in_sizes, int n_in,
                              void* d_out, int out_size) {
    const float* x   = (const float*)d_in[0];
    const void*  ei  = d_in[1];
    const float* W1  = (const float*)d_in[2];
    const float* as1 = (const float*)d_in[3];
    const float* ad1 = (const float*)d_in[4];
    const float* b1  = (const float*)d_in[5];
    const float* W2  = (const float*)d_in[6];
    const float* as2 = (const float*)d_in[7];
    const float* ad2 = (const float*)d_in[8];
    const float* b2  = (const float*)d_in[9];
    const float* W3  = (const float*)d_in[10];
    const float* a3s = (const float*)d_in[11];
    const float* a3d = (const float*)d_in[12];
    const float* b3  = (const float*)d_in[13];
    float* out = (float*)d_out;

    int N = in_sizes[0];
    int E = in_sizes[1] / 2;
    if (N > NMAX) N = NMAX;
    if (E > EMAX) E = EMAX;
    int tot = E + N;

    float* hA; cudaGetSymbolAddress((void**)&hA, d_hA);
    float* hB; cudaGetSymbolAddress((void**)&hB, d_hB);

    init_k<<<(N + 255) / 256, 256>>>(ei, W1, as1, ad1, N);
    int e4_blocks = ((tot + 3) / 4 + 255) / 256;
    int T = e4_blocks * 256;                     // stride between a thread's edges
    hist_k<<<e4_blocks, 256>>>(ei, E, N, T);
    scan_k<<<NBLK, 1024>>>(N);
    scatter_k<<<e4_blocks, 256>>>(ei, E, N, T);

    int agg_blocks = (N * 32 + 255) / 256;

    // layer 1 (rank-1 factorized, fp16 z1 out)
    agg1_k<<<agg_blocks, 256>>>(x, W1, b1, (__half*)hB, N);

    // layer 2: tensor-core GEMM (+fused alphas) + aggregation (+layer-3 feat)
    size_t smem = 2 * 128 * APAD * sizeof(__half);
    cudaFuncSetAttribute(gemm_tc, cudaFuncAttributeMaxDynamicSharedMemorySize, (int)smem);
    gemm_tc<<<296, 256, smem>>>((const __half*)hB, W2, as2, ad2, (__half*)hA, N);
    agg2_k<<<agg_blocks, 256>>>((const __half*)hA, b2, W3, a3s, a3d, N);

    // layer 3
    agg3_k<<<(N * 32 + 255) / 256, 256>>>(b3, out, N);
}